// round 1
// baseline (speedup 1.0000x reference)
#include <cuda_runtime.h>
#include <math.h>

#define NPTS  2048
#define BATCH 8
#define BNT   (BATCH*NPTS)   // 16384
#define KNN   20

// ------------------------- scratch (device globals) -------------------------
__device__ float  d_u[BNT*256];
__device__ float  d_v[BNT*256];
__device__ float  d_umax[BNT*256];
__device__ float  d_umin[BNT*256];
__device__ float  d_cat[BNT*512];
__device__ float  d_h5[(size_t)BNT*1024];
__device__ int    d_idx[BNT*KNN];
__device__ float  d_wv[256*256];
__device__ double d_sum[1024];
__device__ double d_sumsq[1024];
__device__ float  d_scale[1024];
__device__ float  d_shift[1024];

// ------------------------------- KNN ---------------------------------------
__global__ __launch_bounds__(256) void knn_kernel(const float* __restrict__ x) {
    __shared__ float sx[NPTS*3];
    __shared__ float sxx[NPTS];
    int b = blockIdx.x / (NPTS/256);
    int qbase = (blockIdx.x % (NPTS/256)) * 256;
    const float* xb = x + (size_t)b*NPTS*3;
    for (int i = threadIdx.x; i < NPTS*3; i += 256) sx[i] = xb[i];
    __syncthreads();
    for (int i = threadIdx.x; i < NPTS; i += 256) {
        float a0=sx[3*i], a1=sx[3*i+1], a2=sx[3*i+2];
        sxx[i] = a0*a0 + a1*a1 + a2*a2;
    }
    __syncthreads();
    int q = qbase + threadIdx.x;
    float qx=sx[3*q], qy=sx[3*q+1], qz=sx[3*q+2], qq=sxx[q];
    float best[KNN]; int bidx[KNN];
#pragma unroll
    for (int j=0;j<KNN;j++){ best[j]=-3.4e38f; bidx[j]=0; }
    float thr = -3.4e38f;
    for (int m=0;m<NPTS;m++){
        float pd = 2.f*(qx*sx[3*m]+qy*sx[3*m+1]+qz*sx[3*m+2]) - qq - sxx[m];
        if (pd > thr) {
            int j = KNN-1;
            while (j > 0 && best[j-1] < pd) { best[j]=best[j-1]; bidx[j]=bidx[j-1]; j--; }
            best[j]=pd; bidx[j]=m;
            thr = best[KNN-1];
        }
    }
    int base = (b*NPTS+q)*KNN;
#pragma unroll
    for (int j=0;j<KNN;j++) d_idx[base+j] = bidx[j];
}

// ------------------------------- GEMM (NT) ----------------------------------
// C[m][n] = sum_k A[m*lda+k] * B[n*ldb+k];  M = gridDim.y*64, N = gridDim.x*64
__global__ __launch_bounds__(256) void gemm_nt(
    const float* __restrict__ A, int lda,
    const float* __restrict__ Bm, int ldb,
    float* __restrict__ C, int ldc, int Kdim)
{
    __shared__ float As[16][64];
    __shared__ float Bs[16][64];
    int bm = blockIdx.y*64, bn = blockIdx.x*64;
    int tid = threadIdx.x;
    int tm = tid >> 4, tn = tid & 15;
    float acc[4][4];
#pragma unroll
    for (int i=0;i<4;i++)
#pragma unroll
        for (int j=0;j<4;j++) acc[i][j]=0.f;

    for (int k0=0; k0<Kdim; k0+=16) {
        for (int l=tid; l<1024; l+=256) {
            int r = l>>4, c = l&15;
            int kk = k0 + c;
            As[c][r] = (kk < Kdim) ? A[(size_t)(bm+r)*lda + kk] : 0.f;
        }
        for (int l=tid; l<1024; l+=256) {
            int r = l>>4, c = l&15;
            int kk = k0 + c;
            Bs[c][r] = (kk < Kdim) ? Bm[(size_t)(bn+r)*ldb + kk] : 0.f;
        }
        __syncthreads();
#pragma unroll
        for (int kk=0; kk<16; kk++) {
            float4 a  = *(const float4*)&As[kk][tm*4];
            float4 bv = *(const float4*)&Bs[kk][tn*4];
            float av[4]={a.x,a.y,a.z,a.w}, bb[4]={bv.x,bv.y,bv.z,bv.w};
#pragma unroll
            for (int i=0;i<4;i++)
#pragma unroll
                for (int j=0;j<4;j++) acc[i][j] += av[i]*bb[j];
        }
        __syncthreads();
    }
#pragma unroll
    for (int i=0;i<4;i++) {
        float4 r = make_float4(acc[i][0],acc[i][1],acc[i][2],acc[i][3]);
        *(float4*)&C[(size_t)(bm+tm*4+i)*ldc + bn + tn*4] = r;
    }
}

// ------------------------- small helpers -----------------------------------
__global__ void prep_wv(const float* __restrict__ w, int C, int O) {
    int i = blockIdx.x*256 + threadIdx.x;
    if (i < O*C) {
        int o = i / C, c = i - o*C;
        d_wv[i] = w[o*2*C + C + c] - w[o*2*C + c];
    }
}

__global__ void zero_stats() {
    int i = blockIdx.x*256 + threadIdx.x;
    if (i < 1024) { d_sum[i] = 0.0; d_sumsq[i] = 0.0; }
}

// ------------------------- gather + BN stats --------------------------------
__global__ __launch_bounds__(256) void gather_kernel(int O, int iters) {
    int groups = 256 / O;
    int g = threadIdx.x / O;
    int o = threadIdx.x - g*O;
    int ppb = groups * iters;
    int p0 = blockIdx.x * ppb;
    float csum = 0.f, csq = 0.f;
    for (int it = 0; it < iters; it++) {
        int p = p0 + it*groups + g;          // global point index in [0, B*N)
        int b = p >> 11;
        const int* ip = d_idx + p*KNN;
        int ubase = (b << 11) * O;
        float s1=0.f, s2=0.f, umx=-3.4e38f, umn=3.4e38f;
#pragma unroll
        for (int k=0;k<KNN;k++){
            int m = ip[k];
            float uv = d_u[ubase + m*O + o];
            s1 += uv; s2 += uv*uv;
            umx = fmaxf(umx, uv); umn = fminf(umn, uv);
        }
        float vv = d_v[(size_t)p*O + o];
        d_umax[(size_t)p*O + o] = umx;
        d_umin[(size_t)p*O + o] = umn;
        csum += s1 + 20.f*vv;
        csq  += s2 + 2.f*vv*s1 + 20.f*vv*vv;
    }
    __shared__ float ss[256], sq[256];
    ss[threadIdx.x] = csum; sq[threadIdx.x] = csq;
    __syncthreads();
    for (int s = 128; s >= O; s >>= 1) {
        if (threadIdx.x < s) { ss[threadIdx.x] += ss[threadIdx.x+s]; sq[threadIdx.x] += sq[threadIdx.x+s]; }
        __syncthreads();
    }
    if (threadIdx.x < O) {
        atomicAdd(&d_sum[threadIdx.x],   (double)ss[threadIdx.x]);
        atomicAdd(&d_sumsq[threadIdx.x], (double)sq[threadIdx.x]);
    }
}

__global__ void finalize_bn(const float* __restrict__ gw, const float* __restrict__ bw,
                            int O, float invcnt) {
    int o = blockIdx.x*256 + threadIdx.x;
    if (o < O) {
        float mean = (float)(d_sum[o]   * (double)invcnt);
        float msq  = (float)(d_sumsq[o] * (double)invcnt);
        float var  = fmaxf(msq - mean*mean, 0.f);
        float sc = gw[o] * rsqrtf(var + 1e-5f);
        d_scale[o] = sc;
        d_shift[o] = bw[o] - mean*sc;
    }
}

__global__ void edge_out(int O, int coff) {
    int i = blockIdx.x*256 + threadIdx.x;
    if (i < BNT*O) {
        int p = i / O, o = i - p*O;
        float sc = d_scale[o], sh = d_shift[o];
        float ext = (sc >= 0.f) ? d_umax[i] : d_umin[i];
        float h = (d_v[i] + ext)*sc + sh;
        d_cat[(size_t)p*512 + coff + o] = tanhf(h);
    }
}

// ------------------------- head: stats + final reduce -----------------------
__global__ __launch_bounds__(256) void stats_h5(const float* __restrict__ g5,
                                                const float* __restrict__ b5) {
    int ol = threadIdx.x & 31;
    int row = threadIdx.x >> 5;
    int o = blockIdx.x*32 + ol;
    float s = 0.f, q = 0.f;
    for (int m = row; m < BNT; m += 8) {
        float v = d_h5[(size_t)m*1024 + o];
        s += v; q += v*v;
    }
    __shared__ float ss[8][32], sq2[8][32];
    ss[row][ol] = s; sq2[row][ol] = q;
    __syncthreads();
    if (row == 0) {
#pragma unroll
        for (int r=1;r<8;r++){ s += ss[r][ol]; q += sq2[r][ol]; }
        float inv = 1.f / (float)BNT;
        float mean = s*inv;
        float var = fmaxf(q*inv - mean*mean, 0.f);
        float sc = g5[o] * rsqrtf(var + 1e-5f);
        d_scale[o] = sc;
        d_shift[o] = b5[o] - mean*sc;
    }
}

__global__ __launch_bounds__(256) void final5(float* __restrict__ out) {
    int ol = threadIdx.x & 31;
    int row = threadIdx.x >> 5;
    int b = blockIdx.y;
    int o = blockIdx.x*32 + ol;
    float sc = d_scale[o], sh = d_shift[o];
    float mx = -3.4e38f, sm = 0.f;
    for (int n = row; n < NPTS; n += 8) {
        float z = d_h5[(size_t)(b*NPTS + n)*1024 + o]*sc + sh;
        float t = tanhf(z);
        mx = fmaxf(mx, t); sm += t;
    }
    __shared__ float smx[8][32], ssm[8][32];
    smx[row][ol] = mx; ssm[row][ol] = sm;
    __syncthreads();
    if (row == 0) {
#pragma unroll
        for (int r=1;r<8;r++){ mx = fmaxf(mx, smx[r][ol]); sm += ssm[r][ol]; }
        out[b*2048 + o]        = mx;
        out[b*2048 + 1024 + o] = sm * (1.f/NPTS);
    }
}

// ------------------------------- launch -------------------------------------
extern "C" void kernel_launch(void* const* d_in, const int* in_sizes, int n_in,
                              void* d_out, int out_size) {
    const float* x  = (const float*)d_in[0];
    const float* ft = (const float*)d_in[1];
    const float* W[4]  = {(const float*)d_in[2],  (const float*)d_in[5],
                          (const float*)d_in[8],  (const float*)d_in[11]};
    const float* G[4]  = {(const float*)d_in[3],  (const float*)d_in[6],
                          (const float*)d_in[9],  (const float*)d_in[12]};
    const float* Bv[4] = {(const float*)d_in[4],  (const float*)d_in[7],
                          (const float*)d_in[10], (const float*)d_in[13]};
    const float* w5 = (const float*)d_in[14];
    const float* g5 = (const float*)d_in[15];
    const float* b5 = (const float*)d_in[16];
    float* out = (float*)d_out;

    void *pu, *pv, *pcat, *ph5, *pwv;
    cudaGetSymbolAddress(&pu,  d_u);
    cudaGetSymbolAddress(&pv,  d_v);
    cudaGetSymbolAddress(&pcat, d_cat);
    cudaGetSymbolAddress(&ph5, d_h5);
    cudaGetSymbolAddress(&pwv, d_wv);
    float* uP   = (float*)pu;
    float* vP   = (float*)pv;
    float* catP = (float*)pcat;
    float* h5P  = (float*)ph5;
    float* wvP  = (float*)pwv;

    knn_kernel<<<BATCH*(NPTS/256), 256>>>(x);

    const int Cin[4]  = {3, 64, 64, 128};
    const int Oc[4]   = {64, 64, 128, 256};
    const int coff[4] = {0, 64, 128, 256};
    const float* fin = ft;
    int lda = 3;

    for (int blk = 0; blk < 4; blk++) {
        int C = Cin[blk], O = Oc[blk];
        prep_wv<<<(O*C + 255)/256, 256>>>(W[blk], C, O);
        dim3 gg(O/64, BNT/64);
        gemm_nt<<<gg, 256>>>(fin, lda, W[blk], 2*C, uP, O, C);   // u = f * W[:, :C]^T
        gemm_nt<<<gg, 256>>>(fin, lda, wvP,   C,   vP, O, C);    // v = f * (W2-W1)^T
        zero_stats<<<4, 256>>>();
        int iters = 8, groups = 256 / O, ppb = groups * iters;
        gather_kernel<<<BNT/ppb, 256>>>(O, iters);
        finalize_bn<<<(O + 255)/256, 256>>>(G[blk], Bv[blk], O, 1.f/((float)BNT*KNN));
        edge_out<<<(BNT*O)/256, 256>>>(O, coff[blk]);
        fin = catP + coff[blk];
        lda = 512;
    }

    dim3 g5g(1024/64, BNT/64);
    gemm_nt<<<g5g, 256>>>(catP, 512, w5, 512, h5P, 1024, 512);
    stats_h5<<<32, 256>>>(g5, b5);
    dim3 fg(32, BATCH);
    final5<<<fg, 256>>>(out);
}

// round 2
// speedup vs baseline: 4.9410x; 4.9410x over previous
#include <cuda_runtime.h>
#include <math.h>

#define NPTS  2048
#define BATCH 8
#define BNT   (BATCH*NPTS)   // 16384
#define KNN   20

// ------------------------- scratch (device globals) -------------------------
__device__ float  d_uv[(size_t)BNT*512];    // [u | v] interleaved per point, width 2*O
__device__ float  d_umax[(size_t)BNT*256];
__device__ float  d_umin[(size_t)BNT*256];
__device__ float  d_cat[(size_t)BNT*512];
__device__ float  d_h5[(size_t)BNT*1024];
__device__ int    d_idx[BNT*KNN];
__device__ float  d_wcomb[512*128];
__device__ double d_sum[1024];
__device__ double d_sumsq[1024];
__device__ float  d_scale[1024];
__device__ float  d_shift[1024];

// fast tanh: (e^2x - 1)/(e^2x + 1), MUFU-based, rel err ~1e-6
__device__ __forceinline__ float ftanh(float x) {
    x = fminf(fmaxf(x, -15.f), 15.f);
    float e = __expf(2.f * x);
    return __fdividef(e - 1.f, e + 1.f);
}

// ------------------------------- KNN ---------------------------------------
__global__ __launch_bounds__(256) void knn_kernel(const float* __restrict__ x) {
    __shared__ float sx[NPTS*3];
    __shared__ float sxx[NPTS];
    int b = blockIdx.x / (NPTS/256);
    int qbase = (blockIdx.x % (NPTS/256)) * 256;
    const float* xb = x + (size_t)b*NPTS*3;
    for (int i = threadIdx.x; i < NPTS*3; i += 256) sx[i] = xb[i];
    __syncthreads();
    for (int i = threadIdx.x; i < NPTS; i += 256) {
        float a0=sx[3*i], a1=sx[3*i+1], a2=sx[3*i+2];
        sxx[i] = a0*a0 + a1*a1 + a2*a2;
    }
    __syncthreads();
    int q = qbase + threadIdx.x;
    float qx=sx[3*q], qy=sx[3*q+1], qz=sx[3*q+2], qq=sxx[q];
    float best[KNN]; int bidx[KNN];
#pragma unroll
    for (int j=0;j<KNN;j++){ best[j]=-3.4e38f; bidx[j]=0; }
    float thr = -3.4e38f;
    for (int m=0;m<NPTS;m++){
        float pd = 2.f*(qx*sx[3*m]+qy*sx[3*m+1]+qz*sx[3*m+2]) - qq - sxx[m];
        if (pd > thr) {
            // fully-unrolled predicated bubble insert: registers only
            float ins = pd; int insi = m;
#pragma unroll
            for (int j=0;j<KNN;j++){
                float bj = best[j]; int ij = bidx[j];
                bool sw = bj < ins;
                best[j] = sw ? ins  : bj;
                bidx[j] = sw ? insi : ij;
                ins     = sw ? bj   : ins;
                insi    = sw ? ij   : insi;
            }
            thr = best[KNN-1];
        }
    }
    int base = (b*NPTS+q)*KNN;
#pragma unroll
    for (int j=0;j<KNN;j++) d_idx[base+j] = bidx[j];
}

// ------------------------------- GEMM (NT, FFMA2) ---------------------------
// C[m][n] = sum_k A[m*lda+k] * B[n*ldb+k]
// BM=128, BN=128, BK=16, 256 threads, per-thread 8x8 via packed f32x2 FMA.
__global__ __launch_bounds__(256) void gemm_nt2(
    const float* __restrict__ A, int lda,
    const float* __restrict__ Bm, int ldb,
    float* __restrict__ C, int ldc, int Kdim)
{
    __shared__ float As[16][128];
    __shared__ float Bs[16][128];
    int bm = blockIdx.y*128, bn = blockIdx.x*128;
    int tid = threadIdx.x;
    int tm = tid >> 4;   // 0..15
    int tn = tid & 15;   // 0..15

    unsigned long long acc[8][4];
#pragma unroll
    for (int i=0;i<8;i++)
#pragma unroll
        for (int j=0;j<4;j++) acc[i][j]=0ull;

    int scol = tid & 15;
    int srow0 = tid >> 4;
    for (int k0=0; k0<Kdim; k0+=16) {
        int kk0 = k0 + scol;
        bool kok = (kk0 < Kdim);
#pragma unroll
        for (int c=0;c<8;c++){
            int r = c*16 + srow0;
            As[scol][r] = kok ? A[(size_t)(bm+r)*lda + kk0] : 0.f;
            Bs[scol][r] = kok ? Bm[(size_t)(bn+r)*ldb + kk0] : 0.f;
        }
        __syncthreads();
#pragma unroll
        for (int kk=0; kk<16; kk++) {
            float4 t0 = *(const float4*)&As[kk][tm*8];
            float4 t1 = *(const float4*)&As[kk][tm*8+4];
            float af[8] = {t0.x,t0.y,t0.z,t0.w,t1.x,t1.y,t1.z,t1.w};
            const unsigned long long* bp =
                (const unsigned long long*)&Bs[kk][tn*8];
            unsigned long long q0=bp[0], q1=bp[1], q2=bp[2], q3=bp[3];
#pragma unroll
            for (int i=0;i<8;i++){
                unsigned long long ax;
                asm("mov.b64 %0, {%1, %1};" : "=l"(ax) : "f"(af[i]));
                asm("fma.rn.f32x2 %0, %1, %2, %0;" : "+l"(acc[i][0]) : "l"(ax), "l"(q0));
                asm("fma.rn.f32x2 %0, %1, %2, %0;" : "+l"(acc[i][1]) : "l"(ax), "l"(q1));
                asm("fma.rn.f32x2 %0, %1, %2, %0;" : "+l"(acc[i][2]) : "l"(ax), "l"(q2));
                asm("fma.rn.f32x2 %0, %1, %2, %0;" : "+l"(acc[i][3]) : "l"(ax), "l"(q3));
            }
        }
        __syncthreads();
    }
#pragma unroll
    for (int i=0;i<8;i++){
        float o8[8];
#pragma unroll
        for (int j=0;j<4;j++){
            o8[2*j]   = __uint_as_float((unsigned)(acc[i][j] & 0xffffffffull));
            o8[2*j+1] = __uint_as_float((unsigned)(acc[i][j] >> 32));
        }
        size_t off = (size_t)(bm + tm*8 + i)*ldc + bn + tn*8;
        *(float4*)&C[off]   = make_float4(o8[0],o8[1],o8[2],o8[3]);
        *(float4*)&C[off+4] = make_float4(o8[4],o8[5],o8[6],o8[7]);
    }
}

// ------------------------- small helpers -----------------------------------
// wcomb[2O x C]: rows [0,O) = W[:, :C]; rows [O,2O) = W[:, C:2C] - W[:, :C]
__global__ void prep_wcomb(const float* __restrict__ w, int C, int O) {
    int i = blockIdx.x*256 + threadIdx.x;
    if (i < 2*O*C) {
        int r = i / C, c = i - r*C;
        float v;
        if (r < O) v = w[r*2*C + c];
        else { int o = r - O; v = w[o*2*C + C + c] - w[o*2*C + c]; }
        d_wcomb[i] = v;
    }
}

__global__ void zero_stats() {
    int i = blockIdx.x*256 + threadIdx.x;
    if (i < 1024) { d_sum[i] = 0.0; d_sumsq[i] = 0.0; }
}

// ------------------------- gather + BN stats --------------------------------
__global__ __launch_bounds__(256) void gather_kernel(int O, int iters) {
    int groups = 256 / O;
    int g = threadIdx.x / O;
    int o = threadIdx.x - g*O;
    int ppb = groups * iters;
    int p0 = blockIdx.x * ppb;
    int W2 = 2*O;
    float csum = 0.f, csq = 0.f;
    for (int it = 0; it < iters; it++) {
        int p = p0 + it*groups + g;
        int b = p >> 11;
        const int* ip = d_idx + p*KNN;
        int rbase = (b << 11);
        float s1=0.f, s2=0.f, umx=-3.4e38f, umn=3.4e38f;
#pragma unroll
        for (int k=0;k<KNN;k++){
            int m = ip[k];
            float uv = d_uv[(size_t)(rbase + m)*W2 + o];
            s1 += uv; s2 += uv*uv;
            umx = fmaxf(umx, uv); umn = fminf(umn, uv);
        }
        float vv = d_uv[(size_t)p*W2 + O + o];
        d_umax[(size_t)p*O + o] = umx;
        d_umin[(size_t)p*O + o] = umn;
        csum += s1 + 20.f*vv;
        csq  += s2 + 2.f*vv*s1 + 20.f*vv*vv;
    }
    __shared__ float ss[256], sq[256];
    ss[threadIdx.x] = csum; sq[threadIdx.x] = csq;
    __syncthreads();
    for (int s = 128; s >= O; s >>= 1) {
        if (threadIdx.x < s) { ss[threadIdx.x] += ss[threadIdx.x+s]; sq[threadIdx.x] += sq[threadIdx.x+s]; }
        __syncthreads();
    }
    if (threadIdx.x < O) {
        atomicAdd(&d_sum[threadIdx.x],   (double)ss[threadIdx.x]);
        atomicAdd(&d_sumsq[threadIdx.x], (double)sq[threadIdx.x]);
    }
}

__global__ void finalize_bn(const float* __restrict__ gw, const float* __restrict__ bw,
                            int O, float invcnt) {
    int o = blockIdx.x*256 + threadIdx.x;
    if (o < O) {
        float mean = (float)(d_sum[o]   * (double)invcnt);
        float msq  = (float)(d_sumsq[o] * (double)invcnt);
        float var  = fmaxf(msq - mean*mean, 0.f);
        float sc = gw[o] * rsqrtf(var + 1e-5f);
        d_scale[o] = sc;
        d_shift[o] = bw[o] - mean*sc;
    }
}

__global__ void edge_out(int O, int coff) {
    int i = blockIdx.x*256 + threadIdx.x;
    if (i < BNT*O) {
        int p = i / O, o = i - p*O;
        float sc = d_scale[o], sh = d_shift[o];
        float ext = (sc >= 0.f) ? d_umax[i] : d_umin[i];
        float vv = d_uv[(size_t)p*(2*O) + O + o];
        float h = (vv + ext)*sc + sh;
        d_cat[(size_t)p*512 + coff + o] = ftanh(h);
    }
}

// ------------------------- head: stats + final reduce -----------------------
__global__ __launch_bounds__(256) void stats_part() {
    int ol = threadIdx.x & 31;
    int row = threadIdx.x >> 5;
    int o = blockIdx.x*32 + ol;
    int r0 = blockIdx.y*2048;
    float s = 0.f, q = 0.f;
    for (int m = row; m < 2048; m += 8) {
        float v = d_h5[(size_t)(r0 + m)*1024 + o];
        s += v; q += v*v;
    }
    __shared__ float ss[8][32], sq2[8][32];
    ss[row][ol] = s; sq2[row][ol] = q;
    __syncthreads();
    if (row == 0) {
#pragma unroll
        for (int r=1;r<8;r++){ s += ss[r][ol]; q += sq2[r][ol]; }
        atomicAdd(&d_sum[o],   (double)s);
        atomicAdd(&d_sumsq[o], (double)q);
    }
}

__global__ __launch_bounds__(256) void final5(float* __restrict__ out) {
    int ol = threadIdx.x & 31;
    int row = threadIdx.x >> 5;
    int b = blockIdx.y;
    int o = blockIdx.x*32 + ol;
    float sc = d_scale[o], sh = d_shift[o];
    float mx = -3.4e38f, sm = 0.f;
    for (int n = row; n < NPTS; n += 8) {
        float z = d_h5[(size_t)(b*NPTS + n)*1024 + o]*sc + sh;
        float t = ftanh(z);
        mx = fmaxf(mx, t); sm += t;
    }
    __shared__ float smx[8][32], ssm[8][32];
    smx[row][ol] = mx; ssm[row][ol] = sm;
    __syncthreads();
    if (row == 0) {
#pragma unroll
        for (int r=1;r<8;r++){ mx = fmaxf(mx, smx[r][ol]); sm += ssm[r][ol]; }
        out[b*2048 + o]        = mx;
        out[b*2048 + 1024 + o] = sm * (1.f/NPTS);
    }
}

// ------------------------------- launch -------------------------------------
extern "C" void kernel_launch(void* const* d_in, const int* in_sizes, int n_in,
                              void* d_out, int out_size) {
    const float* x  = (const float*)d_in[0];
    const float* ft = (const float*)d_in[1];
    const float* W[4]  = {(const float*)d_in[2],  (const float*)d_in[5],
                          (const float*)d_in[8],  (const float*)d_in[11]};
    const float* G[4]  = {(const float*)d_in[3],  (const float*)d_in[6],
                          (const float*)d_in[9],  (const float*)d_in[12]};
    const float* Bv[4] = {(const float*)d_in[4],  (const float*)d_in[7],
                          (const float*)d_in[10], (const float*)d_in[13]};
    const float* w5 = (const float*)d_in[14];
    const float* g5 = (const float*)d_in[15];
    const float* b5 = (const float*)d_in[16];
    float* out = (float*)d_out;

    void *puv, *pcat, *ph5, *pwc;
    cudaGetSymbolAddress(&puv,  d_uv);
    cudaGetSymbolAddress(&pcat, d_cat);
    cudaGetSymbolAddress(&ph5,  d_h5);
    cudaGetSymbolAddress(&pwc,  d_wcomb);
    float* uvP  = (float*)puv;
    float* catP = (float*)pcat;
    float* h5P  = (float*)ph5;
    float* wcP  = (float*)pwc;

    knn_kernel<<<BATCH*(NPTS/256), 256>>>(x);

    const int Cin[4]  = {3, 64, 64, 128};
    const int Oc[4]   = {64, 64, 128, 256};
    const int coff[4] = {0, 64, 128, 256};
    const float* fin = ft;
    int lda = 3;

    for (int blk = 0; blk < 4; blk++) {
        int C = Cin[blk], O = Oc[blk];
        prep_wcomb<<<(2*O*C + 255)/256, 256>>>(W[blk], C, O);
        dim3 gg(2*O/128, BNT/128);
        gemm_nt2<<<gg, 256>>>(fin, lda, wcP, C, uvP, 2*O, C);   // [u|v]
        zero_stats<<<4, 256>>>();
        int iters = 8, groups = 256 / O, ppb = groups * iters;
        gather_kernel<<<BNT/ppb, 256>>>(O, iters);
        finalize_bn<<<(O + 255)/256, 256>>>(G[blk], Bv[blk], O, 1.f/((float)BNT*KNN));
        edge_out<<<(BNT*O)/256, 256>>>(O, coff[blk]);
        fin = catP + coff[blk];
        lda = 512;
    }

    dim3 g5g(1024/128, BNT/128);
    gemm_nt2<<<g5g, 256>>>(catP, 512, w5, 512, h5P, 1024, 512);
    zero_stats<<<4, 256>>>();
    dim3 sg(32, 8);
    stats_part<<<sg, 256>>>();
    finalize_bn<<<4, 256>>>(g5, b5, 1024, 1.f/(float)BNT);
    dim3 fg(32, BATCH);
    final5<<<fg, 256>>>(out);
}

// round 6
// speedup vs baseline: 6.9788x; 1.4124x over previous
#include <cuda_runtime.h>
#include <cuda_bf16.h>
#include <math.h>
#include <stdint.h>

#define NPTS  2048
#define BATCH 8
#define BNT   (BATCH*NPTS)   // 16384
#define KNN   20

// ------------------------- scratch (device globals) -------------------------
__device__ float          d_uv[(size_t)BNT*512];    // [u | v] per point, width 2*O
__device__ float          d_umax[(size_t)BNT*256];
__device__ float          d_umin[(size_t)BNT*256];
__device__ __nv_bfloat16  d_cat_hi[(size_t)BNT*512];
__device__ __nv_bfloat16  d_cat_lo[(size_t)BNT*512];
__device__ float          d_h5[(size_t)BNT*1024];
__device__ int            d_idx[BNT*KNN];
__device__ float          d_wcomb[512*128];         // fp32 (block 1)
__device__ __nv_bfloat16  d_wch[512*128];
__device__ __nv_bfloat16  d_wcl[512*128];
__device__ __nv_bfloat16  d_w5h[1024*512];
__device__ __nv_bfloat16  d_w5l[1024*512];
__device__ double         d_sum[1024];
__device__ double         d_sumsq[1024];
__device__ float          d_psum[8*1024];
__device__ float          d_psumsq[8*1024];

// fast tanh: (e^2x - 1)/(e^2x + 1), MUFU-based
__device__ __forceinline__ float ftanh(float x) {
    x = fminf(fmaxf(x, -15.f), 15.f);
    float e = __expf(2.f * x);
    return __fdividef(e - 1.f, e + 1.f);
}

__device__ __forceinline__ uint32_t smem_u32(const void* p) {
    uint32_t a;
    asm("{ .reg .u64 t; cvta.to.shared.u64 t, %1; cvt.u32.u64 %0, t; }"
        : "=r"(a) : "l"(p));
    return a;
}
#define SWZ128(off) ((off) ^ (((off) >> 3) & 0x70))

__device__ __forceinline__ void ldsm4(uint32_t& r0, uint32_t& r1, uint32_t& r2,
                                      uint32_t& r3, uint32_t addr) {
    asm volatile("ldmatrix.sync.aligned.m8n8.x4.shared.b16 {%0,%1,%2,%3}, [%4];"
                 : "=r"(r0), "=r"(r1), "=r"(r2), "=r"(r3) : "r"(addr));
}
__device__ __forceinline__ void ldsm2(uint32_t& r0, uint32_t& r1, uint32_t addr) {
    asm volatile("ldmatrix.sync.aligned.m8n8.x2.shared.b16 {%0,%1}, [%2];"
                 : "=r"(r0), "=r"(r1) : "r"(addr));
}
__device__ __forceinline__ void mma16816(float* d, const uint32_t* a, const uint32_t* b) {
    asm volatile("mma.sync.aligned.m16n8k16.row.col.f32.bf16.bf16.f32 "
                 "{%0,%1,%2,%3}, {%4,%5,%6,%7}, {%8,%9}, {%0,%1,%2,%3};"
                 : "+f"(d[0]), "+f"(d[1]), "+f"(d[2]), "+f"(d[3])
                 : "r"(a[0]), "r"(a[1]), "r"(a[2]), "r"(a[3]),
                   "r"(b[0]), "r"(b[1]));
}

// ------------------------------- KNN ---------------------------------------
__global__ __launch_bounds__(256) void knn_kernel(const float* __restrict__ x) {
    __shared__ float sx[NPTS*3];
    __shared__ float sxx[NPTS];
    int b = blockIdx.x / (NPTS/256);
    int qbase = (blockIdx.x % (NPTS/256)) * 256;
    const float* xb = x + (size_t)b*NPTS*3;
    for (int i = threadIdx.x; i < NPTS*3; i += 256) sx[i] = xb[i];
    __syncthreads();
    for (int i = threadIdx.x; i < NPTS; i += 256) {
        float a0=sx[3*i], a1=sx[3*i+1], a2=sx[3*i+2];
        sxx[i] = a0*a0 + a1*a1 + a2*a2;
    }
    __syncthreads();
    int q = qbase + threadIdx.x;
    float qx=sx[3*q], qy=sx[3*q+1], qz=sx[3*q+2], qq=sxx[q];
    float best[KNN]; int bidx[KNN];
#pragma unroll
    for (int j=0;j<KNN;j++){ best[j]=-3.4e38f; bidx[j]=0; }
    float thr = -3.4e38f;
    for (int m=0;m<NPTS;m++){
        float pd = 2.f*(qx*sx[3*m]+qy*sx[3*m+1]+qz*sx[3*m+2]) - qq - sxx[m];
        if (pd > thr) {
            float ins = pd; int insi = m;
#pragma unroll
            for (int j=0;j<KNN;j++){
                float bj = best[j]; int ij = bidx[j];
                bool sw = bj < ins;
                best[j] = sw ? ins  : bj;
                bidx[j] = sw ? insi : ij;
                ins     = sw ? bj   : ins;
                insi    = sw ? ij   : insi;
            }
            thr = best[KNN-1];
        }
    }
    int base = (b*NPTS+q)*KNN;
#pragma unroll
    for (int j=0;j<KNN;j++) d_idx[base+j] = bidx[j];
}

// ------------- HMMA GEMM (NT, bf16 3-term hi/lo error-compensated) ----------
// C[m][n] = sum_k A[m,k]*B[n,k] with A=Ah+Al, B=Bh+Bl (fp32 split to 2x bf16).
// Computes Ah*Bh + Al*Bh + Ah*Bl over concatenated K regions (K' = 3*Kdim).
// BM=BN=128, BK=64 bf16; 256 threads = 2(m) x 4(n) warps; warp tile 64x32.
__global__ __launch_bounds__(256) void gemm_mma(
    const __nv_bfloat16* __restrict__ Ah, const __nv_bfloat16* __restrict__ Al, int lda,
    const __nv_bfloat16* __restrict__ Bh, const __nv_bfloat16* __restrict__ Bl, int ldb,
    float* __restrict__ C, int ldc, int Kdim)
{
    __shared__ __align__(128) uint8_t As[128*128];
    __shared__ __align__(128) uint8_t Bs[128*128];
    int tid = threadIdx.x;
    int lane = tid & 31, wid = tid >> 5;
    int warp_m = wid >> 2, warp_n = wid & 3;
    int bm = blockIdx.y*128, bn = blockIdx.x*128;

    float acc[4][4][4] = {};
    uint32_t sA = smem_u32(As), sB = smem_u32(Bs);

    int base = Kdim >> 6;          // k-tiles per region
    int ktiles = 3*base;
    for (int it = 0; it < ktiles; it++) {
        int grp = it / base;
        int kk = (it - grp*base) << 6;
        const __nv_bfloat16* Ap = (grp == 1) ? Al : Ah;
        const __nv_bfloat16* Bp = (grp == 2) ? Bl : Bh;
#pragma unroll
        for (int i = 0; i < 4; i++) {
            int u = tid + i*256;
            int r = u >> 3, cb = (u & 7) << 4;      // row, col-byte
            uint4 va = *(const uint4*)(Ap + (size_t)(bm + r)*lda + kk + (cb >> 1));
            *(uint4*)(As + SWZ128(r*128 + cb)) = va;
            uint4 vb = *(const uint4*)(Bp + (size_t)(bn + r)*ldb + kk + (cb >> 1));
            *(uint4*)(Bs + SWZ128(r*128 + cb)) = vb;
        }
        __syncthreads();
#pragma unroll
        for (int ks = 0; ks < 4; ks++) {
            int kb = ks*32;  // byte offset of this k16 chunk
            uint32_t a[4][4], b[4][2];
#pragma unroll
            for (int mt = 0; mt < 4; mt++) {
                int row = warp_m*64 + mt*16 + (lane & 15);
                uint32_t ad = sA + SWZ128((uint32_t)(row*128 + kb + ((lane >> 4) << 4)));
                ldsm4(a[mt][0], a[mt][1], a[mt][2], a[mt][3], ad);
            }
#pragma unroll
            for (int nt = 0; nt < 4; nt++) {
                int row = warp_n*32 + nt*8 + (lane & 7);
                uint32_t ad = sB + SWZ128((uint32_t)(row*128 + kb + (((lane >> 3) & 1) << 4)));
                ldsm2(b[nt][0], b[nt][1], ad);
            }
#pragma unroll
            for (int mt = 0; mt < 4; mt++)
#pragma unroll
                for (int nt = 0; nt < 4; nt++)
                    mma16816(acc[mt][nt], a[mt], b[nt]);
        }
        __syncthreads();
    }
#pragma unroll
    for (int mt = 0; mt < 4; mt++) {
        int r0 = bm + warp_m*64 + mt*16 + (lane >> 2);
#pragma unroll
        for (int nt = 0; nt < 4; nt++) {
            int c0 = bn + warp_n*32 + nt*8 + ((lane & 3) << 1);
            *(float2*)&C[(size_t)r0*ldc + c0]     = make_float2(acc[mt][nt][0], acc[mt][nt][1]);
            *(float2*)&C[(size_t)(r0+8)*ldc + c0] = make_float2(acc[mt][nt][2], acc[mt][nt][3]);
        }
    }
}

// ------------------------- GEMM (NT, FFMA2) — block 1 only ------------------
__global__ __launch_bounds__(256) void gemm_nt2(
    const float* __restrict__ A, int lda,
    const float* __restrict__ Bm, int ldb,
    float* __restrict__ C, int ldc, int Kdim)
{
    __shared__ float As[16][128];
    __shared__ float Bs[16][128];
    int bm = blockIdx.y*128, bn = blockIdx.x*128;
    int tid = threadIdx.x;
    int tm = tid >> 4, tn = tid & 15;
    unsigned long long acc[8][4];
#pragma unroll
    for (int i=0;i<8;i++)
#pragma unroll
        for (int j=0;j<4;j++) acc[i][j]=0ull;

    int scol = tid & 15, srow0 = tid >> 4;
    for (int k0=0; k0<Kdim; k0+=16) {
        int kk0 = k0 + scol;
        bool kok = (kk0 < Kdim);
#pragma unroll
        for (int c=0;c<8;c++){
            int r = c*16 + srow0;
            As[scol][r] = kok ? A[(size_t)(bm+r)*lda + kk0] : 0.f;
            Bs[scol][r] = kok ? Bm[(size_t)(bn+r)*ldb + kk0] : 0.f;
        }
        __syncthreads();
#pragma unroll
        for (int kk=0; kk<16; kk++) {
            float4 t0 = *(const float4*)&As[kk][tm*8];
            float4 t1 = *(const float4*)&As[kk][tm*8+4];
            float af[8] = {t0.x,t0.y,t0.z,t0.w,t1.x,t1.y,t1.z,t1.w};
            const unsigned long long* bp = (const unsigned long long*)&Bs[kk][tn*8];
            unsigned long long q0=bp[0], q1=bp[1], q2=bp[2], q3=bp[3];
#pragma unroll
            for (int i=0;i<8;i++){
                unsigned long long ax;
                asm("mov.b64 %0, {%1, %1};" : "=l"(ax) : "f"(af[i]));
                asm("fma.rn.f32x2 %0, %1, %2, %0;" : "+l"(acc[i][0]) : "l"(ax), "l"(q0));
                asm("fma.rn.f32x2 %0, %1, %2, %0;" : "+l"(acc[i][1]) : "l"(ax), "l"(q1));
                asm("fma.rn.f32x2 %0, %1, %2, %0;" : "+l"(acc[i][2]) : "l"(ax), "l"(q2));
                asm("fma.rn.f32x2 %0, %1, %2, %0;" : "+l"(acc[i][3]) : "l"(ax), "l"(q3));
            }
        }
        __syncthreads();
    }
#pragma unroll
    for (int i=0;i<8;i++){
        float o8[8];
#pragma unroll
        for (int j=0;j<4;j++){
            o8[2*j]   = __uint_as_float((unsigned)(acc[i][j] & 0xffffffffull));
            o8[2*j+1] = __uint_as_float((unsigned)(acc[i][j] >> 32));
        }
        size_t off = (size_t)(bm + tm*8 + i)*ldc + bn + tn*8;
        *(float4*)&C[off]   = make_float4(o8[0],o8[1],o8[2],o8[3]);
        *(float4*)&C[off+4] = make_float4(o8[4],o8[5],o8[6],o8[7]);
    }
}

// ------------------------- small helpers -----------------------------------
__global__ void prep_wcomb(const float* __restrict__ w, int C, int O) {
    int i = blockIdx.x*256 + threadIdx.x;
    if (i < 1024) { d_sum[i] = 0.0; d_sumsq[i] = 0.0; }
    if (i < 2*O*C) {
        int r = i / C, c = i - r*C;
        float v;
        if (r < O) v = w[r*2*C + c];
        else { int o = r - O; v = w[o*2*C + C + c] - w[o*2*C + c]; }
        d_wcomb[i] = v;
        __nv_bfloat16 hi = __float2bfloat16(v);
        d_wch[i] = hi;
        d_wcl[i] = __float2bfloat16(v - __bfloat162float(hi));
    }
}

__global__ void prep_w5(const float* __restrict__ w5) {
    int i = blockIdx.x*256 + threadIdx.x;
    if (i < 1024*512) {
        float v = w5[i];
        __nv_bfloat16 hi = __float2bfloat16(v);
        d_w5h[i] = hi;
        d_w5l[i] = __float2bfloat16(v - __bfloat162float(hi));
    }
}

// ------------------------- gather + BN stats --------------------------------
__global__ __launch_bounds__(256) void gather_kernel(int O, int iters) {
    int groups = 256 / O;
    int g = threadIdx.x / O;
    int o = threadIdx.x - g*O;
    int ppb = groups * iters;
    int p0 = blockIdx.x * ppb;
    int W2 = 2*O;
    float csum = 0.f, csq = 0.f;
    for (int it = 0; it < iters; it++) {
        int p = p0 + it*groups + g;
        int b = p >> 11;
        const int* ip = d_idx + p*KNN;
        int rbase = (b << 11);
        float s1=0.f, s2=0.f, umx=-3.4e38f, umn=3.4e38f;
#pragma unroll
        for (int k=0;k<KNN;k++){
            int m = ip[k];
            float uv = d_uv[(size_t)(rbase + m)*W2 + o];
            s1 += uv; s2 += uv*uv;
            umx = fmaxf(umx, uv); umn = fminf(umn, uv);
        }
        float vv = d_uv[(size_t)p*W2 + O + o];
        d_umax[(size_t)p*O + o] = umx;
        d_umin[(size_t)p*O + o] = umn;
        csum += s1 + 20.f*vv;
        csq  += s2 + 2.f*vv*s1 + 20.f*vv*vv;
    }
    __shared__ float ss[256], sq[256];
    ss[threadIdx.x] = csum; sq[threadIdx.x] = csq;
    __syncthreads();
    for (int s = 128; s >= O; s >>= 1) {
        if (threadIdx.x < s) { ss[threadIdx.x] += ss[threadIdx.x+s]; sq[threadIdx.x] += sq[threadIdx.x+s]; }
        __syncthreads();
    }
    if (threadIdx.x < O) {
        atomicAdd(&d_sum[threadIdx.x],   (double)ss[threadIdx.x]);
        atomicAdd(&d_sumsq[threadIdx.x], (double)sq[threadIdx.x]);
    }
}

__global__ void edge_out(int O, int coff, const float* __restrict__ gw,
                         const float* __restrict__ bw, float invcnt) {
    int i = blockIdx.x*256 + threadIdx.x;
    if (i < BNT*O) {
        int p = i / O, o = i - p*O;
        float mean = (float)(d_sum[o]   * (double)invcnt);
        float msq  = (float)(d_sumsq[o] * (double)invcnt);
        float var  = fmaxf(msq - mean*mean, 0.f);
        float sc = gw[o] * rsqrtf(var + 1e-5f);
        float sh = bw[o] - mean*sc;
        float ext = (sc >= 0.f) ? d_umax[i] : d_umin[i];
        float vv = d_uv[(size_t)p*(2*O) + O + o];
        float t = ftanh((vv + ext)*sc + sh);
        __nv_bfloat16 hi = __float2bfloat16(t);
        size_t cidx = (size_t)p*512 + coff + o;
        d_cat_hi[cidx] = hi;
        d_cat_lo[cidx] = __float2bfloat16(t - __bfloat162float(hi));
    }
}

// ------------------------- head: stats + final reduce -----------------------
__global__ __launch_bounds__(256) void stats_part() {
    int ol = threadIdx.x & 31;
    int row = threadIdx.x >> 5;
    int o = blockIdx.x*32 + ol;
    int r0 = blockIdx.y*2048;
    float s = 0.f, q = 0.f;
    for (int m = row; m < 2048; m += 8) {
        float v = d_h5[(size_t)(r0 + m)*1024 + o];
        s += v; q += v*v;
    }
    __shared__ float ss[8][32], sq2[8][32];
    ss[row][ol] = s; sq2[row][ol] = q;
    __syncthreads();
    if (row == 0) {
#pragma unroll
        for (int r=1;r<8;r++){ s += ss[r][ol]; q += sq2[r][ol]; }
        d_psum[blockIdx.y*1024 + o]   = s;
        d_psumsq[blockIdx.y*1024 + o] = q;
    }
}

__global__ __launch_bounds__(256) void final5(const float* __restrict__ g5,
                                              const float* __restrict__ b5,
                                              float* __restrict__ out) {
    int ol = threadIdx.x & 31;
    int row = threadIdx.x >> 5;
    int b = blockIdx.y;
    int o = blockIdx.x*32 + ol;
    double s = 0.0, q = 0.0;
#pragma unroll
    for (int r=0;r<8;r++){ s += (double)d_psum[r*1024+o]; q += (double)d_psumsq[r*1024+o]; }
    float inv = 1.f / (float)BNT;
    float mean = (float)(s*inv);
    float var = fmaxf((float)(q*inv) - mean*mean, 0.f);
    float sc = g5[o] * rsqrtf(var + 1e-5f);
    float sh = b5[o] - mean*sc;
    float mx = -3.4e38f, sm = 0.f;
    for (int n = row; n < NPTS; n += 8) {
        float z = d_h5[(size_t)(b*NPTS + n)*1024 + o]*sc + sh;
        float t = ftanh(z);
        mx = fmaxf(mx, t); sm += t;
    }
    __shared__ float smx[8][32], ssm[8][32];
    smx[row][ol] = mx; ssm[row][ol] = sm;
    __syncthreads();
    if (row == 0) {
#pragma unroll
        for (int r=1;r<8;r++){ mx = fmaxf(mx, smx[r][ol]); sm += ssm[r][ol]; }
        out[b*2048 + o]        = mx;
        out[b*2048 + 1024 + o] = sm * (1.f/NPTS);
    }
}

// ------------------------------- launch -------------------------------------
extern "C" void kernel_launch(void* const* d_in, const int* in_sizes, int n_in,
                              void* d_out, int out_size) {
    const float* x  = (const float*)d_in[0];
    const float* ft = (const float*)d_in[1];
    const float* W[4]  = {(const float*)d_in[2],  (const float*)d_in[5],
                          (const float*)d_in[8],  (const float*)d_in[11]};
    const float* G[4]  = {(const float*)d_in[3],  (const float*)d_in[6],
                          (const float*)d_in[9],  (const float*)d_in[12]};
    const float* Bv[4] = {(const float*)d_in[4],  (const float*)d_in[7],
                          (const float*)d_in[10], (const float*)d_in[13]};
    const float* w5 = (const float*)d_in[14];
    const float* g5 = (const float*)d_in[15];
    const float* b5 = (const float*)d_in[16];
    float* out = (float*)d_out;

    void *puv, *pch, *pcl, *ph5, *pwc, *pwch, *pwcl, *pw5h, *pw5l;
    cudaGetSymbolAddress(&puv,  d_uv);
    cudaGetSymbolAddress(&pch,  d_cat_hi);
    cudaGetSymbolAddress(&pcl,  d_cat_lo);
    cudaGetSymbolAddress(&ph5,  d_h5);
    cudaGetSymbolAddress(&pwc,  d_wcomb);
    cudaGetSymbolAddress(&pwch, d_wch);
    cudaGetSymbolAddress(&pwcl, d_wcl);
    cudaGetSymbolAddress(&pw5h, d_w5h);
    cudaGetSymbolAddress(&pw5l, d_w5l);
    float* uvP = (float*)puv;
    __nv_bfloat16* chP = (__nv_bfloat16*)pch;
    __nv_bfloat16* clP = (__nv_bfloat16*)pcl;
    float* h5P = (float*)ph5;
    float* wcP = (float*)pwc;
    __nv_bfloat16* wchP = (__nv_bfloat16*)pwch;
    __nv_bfloat16* wclP = (__nv_bfloat16*)pwcl;
    __nv_bfloat16* w5hP = (__nv_bfloat16*)pw5h;
    __nv_bfloat16* w5lP = (__nv_bfloat16*)pw5l;

    knn_kernel<<<BATCH*(NPTS/256), 256>>>(x);
    prep_w5<<<(1024*512 + 255)/256, 256>>>(w5);

    const int Cin[4]  = {3, 64, 64, 128};
    const int Oc[4]   = {64, 64, 128, 256};
    const int coff[4] = {0, 64, 128, 256};

    for (int blk = 0; blk < 4; blk++) {
        int C = Cin[blk], O = Oc[blk];
        int pblocks = (2*O*C + 255)/256; if (pblocks < 4) pblocks = 4;
        prep_wcomb<<<pblocks, 256>>>(W[blk], C, O);
        dim3 gg(2*O/128, BNT/128);
        if (blk == 0) {
            gemm_nt2<<<gg, 256>>>(ft, 3, wcP, C, uvP, 2*O, C);
        } else {
            int cin = coff[blk-1];   // INPUT of block blk = OUTPUT of block blk-1
            gemm_mma<<<gg, 256>>>(chP + cin, clP + cin, 512,
                                  wchP, wclP, C, uvP, 2*O, C);
        }
        int iters = 8, groups = 256 / O, ppb = groups * iters;
        gather_kernel<<<BNT/ppb, 256>>>(O, iters);
        edge_out<<<(BNT*O)/256, 256>>>(O, coff[blk], G[blk], Bv[blk],
                                       1.f/((float)BNT*KNN));
    }

    dim3 g5g(1024/128, BNT/128);
    gemm_mma<<<g5g, 256>>>(chP, clP, 512, w5hP, w5lP, 512, h5P, 1024, 512);
    dim3 sg(32, 8);
    stats_part<<<sg, 256>>>();
    dim3 fg(32, BATCH);
    final5<<<fg, 256>>>(g5, b5, out);
}

// round 7
// speedup vs baseline: 7.9548x; 1.1399x over previous
#include <cuda_runtime.h>
#include <cuda_bf16.h>
#include <math.h>
#include <stdint.h>

#define NPTS  2048
#define BATCH 8
#define BNT   (BATCH*NPTS)   // 16384
#define KNN   20

// ------------------------- scratch (device globals) -------------------------
__device__ float          d_uv[(size_t)BNT*512];    // [u | v] per point, width 2*O
__device__ float          d_umax[(size_t)BNT*256];
__device__ float          d_umin[(size_t)BNT*256];
__device__ __nv_bfloat16  d_cat_hi[(size_t)BNT*512];
__device__ __nv_bfloat16  d_cat_lo[(size_t)BNT*512];
__device__ float          d_h5[(size_t)BNT*1024];
__device__ int            d_idx[BNT*KNN];
__device__ float          d_wcomb[128*3];           // fp32 (block 1, K=3)
__device__ __nv_bfloat16  d_wch[98304];
__device__ __nv_bfloat16  d_wcl[98304];
__device__ __nv_bfloat16  d_w5h[1024*512];
__device__ __nv_bfloat16  d_w5l[1024*512];
__device__ double         d_sum[1024];              // 4 regions of 256 (per edge block)
__device__ double         d_sumsq[1024];
__device__ float          d_psum[1024];             // head stats (fp32 atomics)
__device__ float          d_psumsq[1024];

// fast tanh: (e^2x - 1)/(e^2x + 1), MUFU-based
__device__ __forceinline__ float ftanh(float x) {
    x = fminf(fmaxf(x, -15.f), 15.f);
    float e = __expf(2.f * x);
    return __fdividef(e - 1.f, e + 1.f);
}

__device__ __forceinline__ uint32_t smem_u32(const void* p) {
    uint32_t a;
    asm("{ .reg .u64 t; cvta.to.shared.u64 t, %1; cvt.u32.u64 %0, t; }"
        : "=r"(a) : "l"(p));
    return a;
}
#define SWZ128(off) ((off) ^ (((off) >> 3) & 0x70))

__device__ __forceinline__ void cp16(uint32_t dst, const void* src) {
    asm volatile("cp.async.cg.shared.global [%0], [%1], 16;"
                 :: "r"(dst), "l"(src) : "memory");
}
__device__ __forceinline__ void ldsm4(uint32_t& r0, uint32_t& r1, uint32_t& r2,
                                      uint32_t& r3, uint32_t addr) {
    asm volatile("ldmatrix.sync.aligned.m8n8.x4.shared.b16 {%0,%1,%2,%3}, [%4];"
                 : "=r"(r0), "=r"(r1), "=r"(r2), "=r"(r3) : "r"(addr));
}
__device__ __forceinline__ void ldsm2(uint32_t& r0, uint32_t& r1, uint32_t addr) {
    asm volatile("ldmatrix.sync.aligned.m8n8.x2.shared.b16 {%0,%1}, [%2];"
                 : "=r"(r0), "=r"(r1) : "r"(addr));
}
__device__ __forceinline__ void mma16816(float* d, const uint32_t* a, const uint32_t* b) {
    asm volatile("mma.sync.aligned.m16n8k16.row.col.f32.bf16.bf16.f32 "
                 "{%0,%1,%2,%3}, {%4,%5,%6,%7}, {%8,%9}, {%0,%1,%2,%3};"
                 : "+f"(d[0]), "+f"(d[1]), "+f"(d[2]), "+f"(d[3])
                 : "r"(a[0]), "r"(a[1]), "r"(a[2]), "r"(a[3]),
                   "r"(b[0]), "r"(b[1]));
}

// ------------------------------- KNN ---------------------------------------
__global__ __launch_bounds__(256) void knn_kernel(const float* __restrict__ x) {
    __shared__ float sx[NPTS*3];
    __shared__ float sxx[NPTS];
    int b = blockIdx.x / (NPTS/256);
    int qbase = (blockIdx.x % (NPTS/256)) * 256;
    const float* xb = x + (size_t)b*NPTS*3;
    for (int i = threadIdx.x; i < NPTS*3; i += 256) sx[i] = xb[i];
    __syncthreads();
    for (int i = threadIdx.x; i < NPTS; i += 256) {
        float a0=sx[3*i], a1=sx[3*i+1], a2=sx[3*i+2];
        sxx[i] = a0*a0 + a1*a1 + a2*a2;
    }
    __syncthreads();
    int q = qbase + threadIdx.x;
    float qx=sx[3*q], qy=sx[3*q+1], qz=sx[3*q+2], qq=sxx[q];
    float best[KNN]; int bidx[KNN];
#pragma unroll
    for (int j=0;j<KNN;j++){ best[j]=-3.4e38f; bidx[j]=0; }
    float thr = -3.4e38f;
    for (int m=0;m<NPTS;m++){
        float pd = 2.f*(qx*sx[3*m]+qy*sx[3*m+1]+qz*sx[3*m+2]) - qq - sxx[m];
        if (pd > thr) {
            float ins = pd; int insi = m;
#pragma unroll
            for (int j=0;j<KNN;j++){
                float bj = best[j]; int ij = bidx[j];
                bool sw = bj < ins;
                best[j] = sw ? ins  : bj;
                bidx[j] = sw ? insi : ij;
                ins     = sw ? bj   : ins;
                insi    = sw ? ij   : insi;
            }
            thr = best[KNN-1];
        }
    }
    int base = (b*NPTS+q)*KNN;
#pragma unroll
    for (int j=0;j<KNN;j++) d_idx[base+j] = bidx[j];
}

// ------ HMMA GEMM (NT, bf16 3-term hi/lo, cp.async double-buffered) ---------
// C[m][n] = sum_k A[m,k]*B[n,k]; A=Ah+Al, B=Bh+Bl; K' = 3*Kdim regions.
// BM=BN=128, BK=64; 256 threads = 2(m) x 4(n) warps; warp tile 64x32.
// If psum != nullptr, also accumulates per-column sum/sumsq of C via atomics.
__global__ __launch_bounds__(256) void gemm_mma(
    const __nv_bfloat16* __restrict__ Ah, const __nv_bfloat16* __restrict__ Al, int lda,
    const __nv_bfloat16* __restrict__ Bh, const __nv_bfloat16* __restrict__ Bl, int ldb,
    float* __restrict__ C, int ldc, int Kdim,
    float* psum, float* psumsq)
{
    extern __shared__ __align__(128) uint8_t smemraw[];
    uint32_t sbase = smem_u32(smemraw);
    int tid = threadIdx.x;
    int lane = tid & 31, wid = tid >> 5;
    int warp_m = wid >> 2, warp_n = wid & 3;
    int bm = blockIdx.y*128, bn = blockIdx.x*128;

    float acc[4][4][4] = {};

    int base = Kdim >> 6;          // k-tiles per region
    int ktiles = 3*base;

    // prologue: stage 0
    {
        int grp = 0, kk = 0;
        const __nv_bfloat16* Ap = Ah; const __nv_bfloat16* Bp = Bh;
        (void)grp;
#pragma unroll
        for (int i = 0; i < 4; i++) {
            int u = tid + i*256;
            int r = u >> 3, cb = (u & 7) << 4;
            cp16(sbase + SWZ128(r*128 + cb),        Ap + (size_t)(bm + r)*lda + kk + (cb >> 1));
            cp16(sbase + 16384 + SWZ128(r*128 + cb), Bp + (size_t)(bn + r)*ldb + kk + (cb >> 1));
        }
        asm volatile("cp.async.commit_group;" ::: "memory");
    }

    for (int it = 0; it < ktiles; it++) {
        if (it + 1 < ktiles) {
            int nt2 = it + 1;
            int grp = nt2 / base;
            int kk = (nt2 - grp*base) << 6;
            const __nv_bfloat16* Ap = (grp == 1) ? Al : Ah;
            const __nv_bfloat16* Bp = (grp == 2) ? Bl : Bh;
            uint32_t sa = sbase + ((nt2 & 1) ? 32768u : 0u);
#pragma unroll
            for (int i = 0; i < 4; i++) {
                int u = tid + i*256;
                int r = u >> 3, cb = (u & 7) << 4;
                cp16(sa + SWZ128(r*128 + cb),         Ap + (size_t)(bm + r)*lda + kk + (cb >> 1));
                cp16(sa + 16384 + SWZ128(r*128 + cb), Bp + (size_t)(bn + r)*ldb + kk + (cb >> 1));
            }
            asm volatile("cp.async.commit_group;" ::: "memory");
            asm volatile("cp.async.wait_group 1;" ::: "memory");
        } else {
            asm volatile("cp.async.wait_group 0;" ::: "memory");
        }
        __syncthreads();

        uint32_t sA = sbase + ((it & 1) ? 32768u : 0u);
        uint32_t sB = sA + 16384;
#pragma unroll
        for (int ks = 0; ks < 4; ks++) {
            int kb = ks*32;
            uint32_t a[4][4], b[4][2];
#pragma unroll
            for (int mt = 0; mt < 4; mt++) {
                int row = warp_m*64 + mt*16 + (lane & 15);
                uint32_t ad = sA + SWZ128((uint32_t)(row*128 + kb + ((lane >> 4) << 4)));
                ldsm4(a[mt][0], a[mt][1], a[mt][2], a[mt][3], ad);
            }
#pragma unroll
            for (int nt = 0; nt < 4; nt++) {
                int row = warp_n*32 + nt*8 + (lane & 7);
                uint32_t ad = sB + SWZ128((uint32_t)(row*128 + kb + (((lane >> 3) & 1) << 4)));
                ldsm2(b[nt][0], b[nt][1], ad);
            }
#pragma unroll
            for (int mt = 0; mt < 4; mt++)
#pragma unroll
                for (int nt = 0; nt < 4; nt++)
                    mma16816(acc[mt][nt], a[mt], b[nt]);
        }
        __syncthreads();   // compute done before next prefetch overwrites buffer
    }

#pragma unroll
    for (int mt = 0; mt < 4; mt++) {
        int r0 = bm + warp_m*64 + mt*16 + (lane >> 2);
#pragma unroll
        for (int nt = 0; nt < 4; nt++) {
            int c0 = bn + warp_n*32 + nt*8 + ((lane & 3) << 1);
            *(float2*)&C[(size_t)r0*ldc + c0]     = make_float2(acc[mt][nt][0], acc[mt][nt][1]);
            *(float2*)&C[(size_t)(r0+8)*ldc + c0] = make_float2(acc[mt][nt][2], acc[mt][nt][3]);
        }
    }

    if (psum) {
#pragma unroll
        for (int nt = 0; nt < 4; nt++) {
            float s0=0.f, s1=0.f, q0=0.f, q1=0.f;
#pragma unroll
            for (int mt = 0; mt < 4; mt++) {
                float v0=acc[mt][nt][0], v1=acc[mt][nt][1];
                float v2=acc[mt][nt][2], v3=acc[mt][nt][3];
                s0 += v0+v2; s1 += v1+v3;
                q0 += v0*v0 + v2*v2; q1 += v1*v1 + v3*v3;
            }
#pragma unroll
            for (int off = 16; off >= 4; off >>= 1) {
                s0 += __shfl_down_sync(0xffffffffu, s0, off);
                s1 += __shfl_down_sync(0xffffffffu, s1, off);
                q0 += __shfl_down_sync(0xffffffffu, q0, off);
                q1 += __shfl_down_sync(0xffffffffu, q1, off);
            }
            if (lane < 4) {
                int c0 = bn + warp_n*32 + nt*8 + lane*2;
                atomicAdd(&psum[c0],     s0);
                atomicAdd(&psum[c0+1],   s1);
                atomicAdd(&psumsq[c0],   q0);
                atomicAdd(&psumsq[c0+1], q1);
            }
        }
    }
}

// ------------------------- block-1 projection (K=3) -------------------------
__global__ __launch_bounds__(256) void uv1_kernel(const float* __restrict__ ft) {
    int p = blockIdx.x*2 + (threadIdx.x >> 7);
    int o = threadIdx.x & 127;
    float x0 = ft[p*3], x1 = ft[p*3+1], x2 = ft[p*3+2];
    float r = x0*d_wcomb[o*3] + x1*d_wcomb[o*3+1] + x2*d_wcomb[o*3+2];
    d_uv[(size_t)p*128 + o] = r;
}

// --------------------- prep: zero stats + split all weights -----------------
__device__ __forceinline__ void split_w(const float* __restrict__ w, int C, int O,
                                        int j, __nv_bfloat16* dh, __nv_bfloat16* dl) {
    int r = j / C, c = j - r*C;
    float v = (r < O) ? w[r*2*C + c]
                      : (w[(r-O)*2*C + C + c] - w[(r-O)*2*C + c]);
    __nv_bfloat16 hi = __float2bfloat16(v);
    dh[j] = hi;
    dl[j] = __float2bfloat16(v - __bfloat162float(hi));
}

__global__ void prep_all(const float* __restrict__ w1, const float* __restrict__ w2,
                         const float* __restrict__ w3, const float* __restrict__ w4,
                         const float* __restrict__ w5) {
    int i = blockIdx.x*256 + threadIdx.x;
    if (i < 1024) {
        d_sum[i] = 0.0; d_sumsq[i] = 0.0;
        d_psum[i] = 0.f; d_psumsq[i] = 0.f;
    } else if (i < 1408) {                     // block1 fp32 wcomb (128 x 3)
        int j = i - 1024;
        int r = j / 3, c = j - r*3;
        float v = (r < 64) ? w1[r*6 + c] : (w1[(r-64)*6 + 3 + c] - w1[(r-64)*6 + c]);
        d_wcomb[j] = v;
    } else if (i < 9600) {                     // block2: 128 x 64
        split_w(w2, 64, 64, i - 1408, d_wch, d_wcl);
    } else if (i < 25984) {                    // block3: 256 x 64
        split_w(w3, 64, 128, i - 9600, d_wch + 8192, d_wcl + 8192);
    } else if (i < 91520) {                    // block4: 512 x 128
        split_w(w4, 128, 256, i - 25984, d_wch + 24576, d_wcl + 24576);
    } else if (i < 615808) {                   // head: 1024 x 512
        int j = i - 91520;
        float v = w5[j];
        __nv_bfloat16 hi = __float2bfloat16(v);
        d_w5h[j] = hi;
        d_w5l[j] = __float2bfloat16(v - __bfloat162float(hi));
    }
}

// ------------------------- gather + BN stats --------------------------------
__global__ __launch_bounds__(256) void gather_kernel(int O, int iters, int soff) {
    int groups = 256 / O;
    int g = threadIdx.x / O;
    int o = threadIdx.x - g*O;
    int ppb = groups * iters;
    int p0 = blockIdx.x * ppb;
    int W2 = 2*O;
    float csum = 0.f, csq = 0.f;
    for (int it = 0; it < iters; it++) {
        int p = p0 + it*groups + g;
        int b = p >> 11;
        const int* ip = d_idx + p*KNN;
        int rbase = (b << 11);
        float s1=0.f, s2=0.f, umx=-3.4e38f, umn=3.4e38f;
#pragma unroll
        for (int k=0;k<KNN;k++){
            int m = ip[k];
            float uv = d_uv[(size_t)(rbase + m)*W2 + o];
            s1 += uv; s2 += uv*uv;
            umx = fmaxf(umx, uv); umn = fminf(umn, uv);
        }
        float vv = d_uv[(size_t)p*W2 + O + o];
        d_umax[(size_t)p*O + o] = umx;
        d_umin[(size_t)p*O + o] = umn;
        csum += s1 + 20.f*vv;
        csq  += s2 + 2.f*vv*s1 + 20.f*vv*vv;
    }
    __shared__ float ss[256], sq[256];
    ss[threadIdx.x] = csum; sq[threadIdx.x] = csq;
    __syncthreads();
    for (int s = 128; s >= O; s >>= 1) {
        if (threadIdx.x < s) { ss[threadIdx.x] += ss[threadIdx.x+s]; sq[threadIdx.x] += sq[threadIdx.x+s]; }
        __syncthreads();
    }
    if (threadIdx.x < O) {
        atomicAdd(&d_sum[soff + threadIdx.x],   (double)ss[threadIdx.x]);
        atomicAdd(&d_sumsq[soff + threadIdx.x], (double)sq[threadIdx.x]);
    }
}

__global__ void edge_out(int O, int coff, int soff, const float* __restrict__ gw,
                         const float* __restrict__ bw, float invcnt) {
    int i = blockIdx.x*256 + threadIdx.x;
    if (i < BNT*O) {
        int p = i / O, o = i - p*O;
        float mean = (float)(d_sum[soff+o]   * (double)invcnt);
        float msq  = (float)(d_sumsq[soff+o] * (double)invcnt);
        float var  = fmaxf(msq - mean*mean, 0.f);
        float sc = gw[o] * rsqrtf(var + 1e-5f);
        float sh = bw[o] - mean*sc;
        float ext = (sc >= 0.f) ? d_umax[i] : d_umin[i];
        float vv = d_uv[(size_t)p*(2*O) + O + o];
        float t = ftanh((vv + ext)*sc + sh);
        __nv_bfloat16 hi = __float2bfloat16(t);
        size_t cidx = (size_t)p*512 + coff + o;
        d_cat_hi[cidx] = hi;
        d_cat_lo[cidx] = __float2bfloat16(t - __bfloat162float(hi));
    }
}

// ------------------------- head: final reduce --------------------------------
__global__ __launch_bounds__(256) void final5(const float* __restrict__ g5,
                                              const float* __restrict__ b5,
                                              float* __restrict__ out) {
    int ol = threadIdx.x & 31;
    int row = threadIdx.x >> 5;
    int b = blockIdx.y;
    int o = blockIdx.x*32 + ol;
    float inv = 1.f / (float)BNT;
    float mean = d_psum[o] * inv;
    float var = fmaxf(d_psumsq[o]*inv - mean*mean, 0.f);
    float sc = g5[o] * rsqrtf(var + 1e-5f);
    float sh = b5[o] - mean*sc;
    float mx = -3.4e38f, sm = 0.f;
    for (int n = row; n < NPTS; n += 8) {
        float z = d_h5[(size_t)(b*NPTS + n)*1024 + o]*sc + sh;
        float t = ftanh(z);
        mx = fmaxf(mx, t); sm += t;
    }
    __shared__ float smx[8][32], ssm[8][32];
    smx[row][ol] = mx; ssm[row][ol] = sm;
    __syncthreads();
    if (row == 0) {
#pragma unroll
        for (int r=1;r<8;r++){ mx = fmaxf(mx, smx[r][ol]); sm += ssm[r][ol]; }
        out[b*2048 + o]        = mx;
        out[b*2048 + 1024 + o] = sm * (1.f/NPTS);
    }
}

// ------------------------------- launch -------------------------------------
#define GEMM_SMEM 65536

extern "C" void kernel_launch(void* const* d_in, const int* in_sizes, int n_in,
                              void* d_out, int out_size) {
    const float* x  = (const float*)d_in[0];
    const float* ft = (const float*)d_in[1];
    const float* W[4]  = {(const float*)d_in[2],  (const float*)d_in[5],
                          (const float*)d_in[8],  (const float*)d_in[11]};
    const float* G[4]  = {(const float*)d_in[3],  (const float*)d_in[6],
                          (const float*)d_in[9],  (const float*)d_in[12]};
    const float* Bv[4] = {(const float*)d_in[4],  (const float*)d_in[7],
                          (const float*)d_in[10], (const float*)d_in[13]};
    const float* w5 = (const float*)d_in[14];
    const float* g5 = (const float*)d_in[15];
    const float* b5 = (const float*)d_in[16];
    float* out = (float*)d_out;

    cudaFuncSetAttribute(gemm_mma, cudaFuncAttributeMaxDynamicSharedMemorySize,
                         GEMM_SMEM);

    void *puv, *pch, *pcl, *ph5, *pwch, *pwcl, *pw5h, *pw5l, *pps, *ppq;
    cudaGetSymbolAddress(&puv,  d_uv);
    cudaGetSymbolAddress(&pch,  d_cat_hi);
    cudaGetSymbolAddress(&pcl,  d_cat_lo);
    cudaGetSymbolAddress(&ph5,  d_h5);
    cudaGetSymbolAddress(&pwch, d_wch);
    cudaGetSymbolAddress(&pwcl, d_wcl);
    cudaGetSymbolAddress(&pw5h, d_w5h);
    cudaGetSymbolAddress(&pw5l, d_w5l);
    cudaGetSymbolAddress(&pps,  d_psum);
    cudaGetSymbolAddress(&ppq,  d_psumsq);
    float* uvP = (float*)puv;
    __nv_bfloat16* chP = (__nv_bfloat16*)pch;
    __nv_bfloat16* clP = (__nv_bfloat16*)pcl;
    float* h5P = (float*)ph5;
    __nv_bfloat16* wchP = (__nv_bfloat16*)pwch;
    __nv_bfloat16* wclP = (__nv_bfloat16*)pwcl;
    __nv_bfloat16* w5hP = (__nv_bfloat16*)pw5h;
    __nv_bfloat16* w5lP = (__nv_bfloat16*)pw5l;

    prep_all<<<2406, 256>>>(W[0], W[1], W[2], W[3], w5);
    knn_kernel<<<BATCH*(NPTS/256), 256>>>(x);

    const int Cin[4]  = {3, 64, 64, 128};
    const int Oc[4]   = {64, 64, 128, 256};
    const int coff[4] = {0, 64, 128, 256};
    const int boff[4] = {0, 0, 8192, 24576};

    for (int blk = 0; blk < 4; blk++) {
        int C = Cin[blk], O = Oc[blk];
        if (blk == 0) {
            uv1_kernel<<<BNT/2, 256>>>(ft);
        } else {
            int cin = coff[blk-1];   // input = previous block's output columns
            dim3 gg(2*O/128, BNT/128);
            gemm_mma<<<gg, 256, GEMM_SMEM>>>(chP + cin, clP + cin, 512,
                                             wchP + boff[blk], wclP + boff[blk], C,
                                             uvP, 2*O, C, nullptr, nullptr);
        }
        int iters = 8, groups = 256 / O, ppb = groups * iters;
        gather_kernel<<<BNT/ppb, 256>>>(O, iters, blk*256);
        edge_out<<<(BNT*O)/256, 256>>>(O, coff[blk], blk*256, G[blk], Bv[blk],
                                       1.f/((float)BNT*KNN));
    }

    dim3 g5g(1024/128, BNT/128);
    gemm_mma<<<g5g, 256, GEMM_SMEM>>>(chP, clP, 512, w5hP, w5lP, 512,
                                      h5P, 1024, 512, (float*)pps, (float*)ppq);
    dim3 fg(32, BATCH);
    final5<<<fg, 256>>>(g5, b5, out);
}